// round 9
// baseline (speedup 1.0000x reference)
#include <cuda_runtime.h>
#include <math.h>
#include <stdint.h>

#define DM    4096
#define LD    512
#define BB    4
#define SP    4096
#define STOT  4097
#define NFB   74     /* flash blocks per batch */
#define BUFB  16384  /* one row: DM * 4 bytes */
#define NBUF  6      /* 96 KB ring -> 2 CTAs/SM */

// -------------------- device scratch --------------------
__device__ float g_Cq[BB * DM];
__device__ float g_Qc[BB * DM];
__device__ float g_Qr[BB * DM];
__device__ float g_u [BB * LD];
__device__ float g_t [BB * DM];
__device__ float g_m [BB * NFB];
__device__ float g_l [BB * NFB];
__device__ float g_acc[(size_t)BB * NFB * DM];   // 4.9 MB flash partials
__device__ float g_p [BB * DM];
__device__ float g_a [BB * LD];
__device__ float g_av[BB * DM];

// -------------------- ptx helpers --------------------
__device__ __forceinline__ uint32_t s2u(const void* p) {
    return (uint32_t)__cvta_generic_to_shared(p);
}
#define BAR_INIT(bar, cnt) \
    asm volatile("mbarrier.init.shared.b64 [%0], %1;" :: "r"(bar), "r"(cnt) : "memory")
#define BAR_EXPECT(bar, bytes) \
    asm volatile("mbarrier.arrive.expect_tx.shared.b64 _, [%0], %1;" :: "r"(bar), "r"(bytes) : "memory")
#define BAR_ARRIVE(bar) \
    asm volatile("mbarrier.arrive.shared.b64 _, [%0];" :: "r"(bar) : "memory")
#define BULK_G2S(dst, src, bytes, bar) \
    asm volatile("cp.async.bulk.shared::cluster.global.mbarrier::complete_tx::bytes [%0], [%1], %2, [%3];" \
                 :: "r"(dst), "l"(src), "r"(bytes), "r"(bar) : "memory")
#define FENCE_ASYNC() \
    asm volatile("fence.proxy.async.shared::cta;" ::: "memory")

__device__ __forceinline__ void bar_wait(uint32_t bar, uint32_t parity) {
    asm volatile(
        "{\n\t.reg .pred P;\n"
        "LW_%=:\n\t"
        "mbarrier.try_wait.parity.shared.b64 P, [%0], %1, 0x989680;\n\t"
        "@P bra LD_%=;\n\t"
        "bra LW_%=;\n"
        "LD_%=:\n\t}"
        :: "r"(bar), "r"(parity) : "memory");
}

__device__ __forceinline__ void fma4(float4& a, float s, const float4& v) {
    a.x += s * v.x; a.y += s * v.y; a.z += s * v.z; a.w += s * v.w;
}
__device__ __forceinline__ float dot4(const float4& a, const float4& b) {
    return a.x * b.x + a.y * b.y + a.z * b.z + a.w * b.w;
}

// -------------------- zero atomic targets --------------------
__global__ void k_zero(float* __restrict__ out) {
    int i = blockIdx.x * blockDim.x + threadIdx.x;
    int stride = gridDim.x * blockDim.x;
    for (int j = i; j < BB * DM; j += stride) {
        g_Cq[j] = 0.f; g_Qc[j] = 0.f; g_Qr[j] = 0.f;
        g_t[j] = 0.f; g_av[j] = 0.f; out[j] = 0.f;
    }
    for (int j = i; j < BB * LD; j += stride) { g_a[j] = 0.f; g_u[j] = 0.f; }
}

// ==================== bulk-pipelined forward gemv ====================
// Y[b][:] += X[b][:] @ W; 6x16KB ring, 2 CTAs/SM. blockIdx.y picks matrix.
__global__ __launch_bounds__(256) void k_fw(
    const float* __restrict__ X,
    const float* __restrict__ W0, const float* __restrict__ W1,
    float* __restrict__ Y0, float* __restrict__ Y1)
{
    const float* W = blockIdx.y ? W1 : W0;
    float*       Y = blockIdx.y ? Y1 : Y0;
    extern __shared__ __align__(16) unsigned char sm[];
    float4* bufs = (float4*)sm;                       // NBUF * 1024 float4
    float*  sxv  = (float*)(sm + NBUF * BUFB);        // [BB][32]
    uint32_t sbase = s2u(sm);
    uint32_t bfull = sbase + NBUF * BUFB + 512;
    uint32_t bempt = bfull + NBUF * 8;
    int tid = threadIdx.x;

    int nblk = gridDim.x * gridDim.y / (blockIdx.y ? 1 : 1); // rows split over gridDim.x only
    (void)nblk;
    int r0 = (int)(((long long)blockIdx.x * DM) / gridDim.x);
    int r1 = (int)(((long long)(blockIdx.x + 1) * DM) / gridDim.x);
    int R  = r1 - r0;

    if (tid == 0) {
        #pragma unroll
        for (int i = 0; i < NBUF; i++) { BAR_INIT(bfull + i * 8, 1); BAR_INIT(bempt + i * 8, 256); }
    }
    for (int i = tid; i < BB * R; i += 256) {
        int bb = i / R, rr = i - bb * R;
        sxv[bb * 32 + rr] = X[bb * DM + r0 + rr];
    }
    __syncthreads();
    FENCE_ASYNC();

    if (tid == 0) {
        int np = R < NBUF ? R : NBUF;
        for (int i = 0; i < np; i++) {
            BAR_EXPECT(bfull + i * 8, BUFB);
            BULK_G2S(sbase + i * BUFB, W + (size_t)(r0 + i) * DM, BUFB, bfull + i * 8);
        }
    }

    float4 a0[4] = {{0,0,0,0},{0,0,0,0},{0,0,0,0},{0,0,0,0}};
    float4 a1[4] = {{0,0,0,0},{0,0,0,0},{0,0,0,0},{0,0,0,0}};
    float4 a2[4] = {{0,0,0,0},{0,0,0,0},{0,0,0,0},{0,0,0,0}};
    float4 a3[4] = {{0,0,0,0},{0,0,0,0},{0,0,0,0},{0,0,0,0}};

    int buf = 0; uint32_t ph = 0;
    for (int rr = 0; rr < R; rr++) {
        bar_wait(bfull + buf * 8, ph);
        float x0 = sxv[0 * 32 + rr], x1 = sxv[1 * 32 + rr];
        float x2 = sxv[2 * 32 + rr], x3 = sxv[3 * 32 + rr];
        #pragma unroll
        for (int s = 0; s < 4; s++) {
            float4 wv = bufs[buf * 1024 + tid + 256 * s];
            fma4(a0[s], x0, wv); fma4(a1[s], x1, wv);
            fma4(a2[s], x2, wv); fma4(a3[s], x3, wv);
        }
        BAR_ARRIVE(bempt + buf * 8);
        if (tid == 0 && rr + NBUF < R) {
            bar_wait(bempt + buf * 8, ph);
            BAR_EXPECT(bfull + buf * 8, BUFB);
            BULK_G2S(sbase + buf * BUFB, W + (size_t)(r0 + rr + NBUF) * DM, BUFB, bfull + buf * 8);
        }
        if (++buf == NBUF) { buf = 0; ph ^= 1; }
    }

    #pragma unroll
    for (int s = 0; s < 4; s++) {
        int j = (tid + 256 * s) * 4;
        atomicAdd(&Y[0 * DM + j + 0], a0[s].x); atomicAdd(&Y[0 * DM + j + 1], a0[s].y);
        atomicAdd(&Y[0 * DM + j + 2], a0[s].z); atomicAdd(&Y[0 * DM + j + 3], a0[s].w);
        atomicAdd(&Y[1 * DM + j + 0], a1[s].x); atomicAdd(&Y[1 * DM + j + 1], a1[s].y);
        atomicAdd(&Y[1 * DM + j + 2], a1[s].z); atomicAdd(&Y[1 * DM + j + 3], a1[s].w);
        atomicAdd(&Y[2 * DM + j + 0], a2[s].x); atomicAdd(&Y[2 * DM + j + 1], a2[s].y);
        atomicAdd(&Y[2 * DM + j + 2], a2[s].z); atomicAdd(&Y[2 * DM + j + 3], a2[s].w);
        atomicAdd(&Y[3 * DM + j + 0], a3[s].x); atomicAdd(&Y[3 * DM + j + 1], a3[s].y);
        atomicAdd(&Y[3 * DM + j + 2], a3[s].z); atomicAdd(&Y[3 * DM + j + 3], a3[s].w);
    }
}

// ==================== bulk transposed gemv, sync-free (atomics) ============
// Y[b][r] += dot(W[r][:DM], Q[b][:]). Y must be pre-zeroed.
__global__ __launch_bounds__(256) void k_tr(
    const float* __restrict__ Q,
    const float* __restrict__ W, size_t ldw,
    float* __restrict__ Y, int ystride, int rows)
{
    extern __shared__ __align__(16) unsigned char sm[];
    float4* bufs = (float4*)sm;
    uint32_t sbase = s2u(sm);
    uint32_t bfull = sbase + NBUF * BUFB;
    uint32_t bempt = bfull + NBUF * 8;
    int tid  = threadIdx.x;
    int lane = tid & 31;

    int r0 = (int)(((long long)blockIdx.x * rows) / gridDim.x);
    int r1 = (int)(((long long)(blockIdx.x + 1) * rows) / gridDim.x);
    int R  = r1 - r0;

    if (tid == 0) {
        #pragma unroll
        for (int i = 0; i < NBUF; i++) { BAR_INIT(bfull + i * 8, 1); BAR_INIT(bempt + i * 8, 256); }
    }
    __syncthreads();
    FENCE_ASYNC();
    if (tid == 0) {
        int np = R < NBUF ? R : NBUF;
        for (int i = 0; i < np; i++) {
            BAR_EXPECT(bfull + i * 8, BUFB);
            BULK_G2S(sbase + i * BUFB, W + (size_t)(r0 + i) * ldw, BUFB, bfull + i * 8);
        }
    }

    const float4* Q4 = (const float4*)Q;
    float4 q[BB][4];
    #pragma unroll
    for (int b = 0; b < BB; b++)
        #pragma unroll
        for (int s = 0; s < 4; s++)
            q[b][s] = Q4[b * 1024 + tid + 256 * s];

    int buf = 0; uint32_t ph = 0;
    for (int rr = 0; rr < R; rr++) {
        bar_wait(bfull + buf * 8, ph);
        float p0 = 0.f, p1 = 0.f, p2 = 0.f, p3 = 0.f;
        #pragma unroll
        for (int s = 0; s < 4; s++) {
            float4 wv = bufs[buf * 1024 + tid + 256 * s];
            p0 += dot4(wv, q[0][s]); p1 += dot4(wv, q[1][s]);
            p2 += dot4(wv, q[2][s]); p3 += dot4(wv, q[3][s]);
        }
        BAR_ARRIVE(bempt + buf * 8);
        if (tid == 0 && rr + NBUF < R) {
            bar_wait(bempt + buf * 8, ph);
            BAR_EXPECT(bfull + buf * 8, BUFB);
            BULK_G2S(sbase + buf * BUFB, W + (size_t)(r0 + rr + NBUF) * ldw, BUFB, bfull + buf * 8);
        }
        #pragma unroll
        for (int o = 16; o > 0; o >>= 1) {
            p0 += __shfl_xor_sync(0xffffffffu, p0, o);
            p1 += __shfl_xor_sync(0xffffffffu, p1, o);
            p2 += __shfl_xor_sync(0xffffffffu, p2, o);
            p3 += __shfl_xor_sync(0xffffffffu, p3, o);
        }
        if (lane == 0) {
            atomicAdd(&Y[0 * ystride + r0 + rr], p0);
            atomicAdd(&Y[1 * ystride + r0 + rr], p1);
            atomicAdd(&Y[2 * ystride + r0 + rr], p2);
            atomicAdd(&Y[3 * ystride + r0 + rr], p3);
        }
        if (++buf == NBUF) { buf = 0; ph ^= 1; }
    }
}

// ==================== flash v3: persistent ring + group-of-6 softmax ========
__global__ __launch_bounds__(256) void k_flash(
    const float* __restrict__ x, const float* __restrict__ past)
{
    int b    = blockIdx.y;
    int cx   = blockIdx.x;
    int tid  = threadIdx.x;
    int wid  = tid >> 5;
    int lane = tid & 31;
    extern __shared__ __align__(16) unsigned char sm[];
    float4* bufs = (float4*)sm;                       // NBUF * 1024 float4
    float*  sred = (float*)(sm + NBUF * BUFB);        // [2][NBUF*8]
    uint32_t sbase = s2u(sm);
    uint32_t bfull = sbase + NBUF * BUFB + 512;
    uint32_t bempt = bfull + NBUF * 8;

    int r0 = (int)(((long long)cx * STOT) / NFB);
    int r1 = (int)(((long long)(cx + 1) * STOT) / NFB);
    int R  = r1 - r0;

    if (tid == 0) {
        #pragma unroll
        for (int i = 0; i < NBUF; i++) { BAR_INIT(bfull + i * 8, 1); BAR_INIT(bempt + i * 8, 256); }
    }
    __syncthreads();
    FENCE_ASYNC();
    if (tid == 0) {
        int np = R < NBUF ? R : NBUF;
        for (int i = 0; i < np; i++) {
            int s = r0 + i;
            const float* src = (s < SP) ? past + ((size_t)b * SP + s) * DM : x + (size_t)b * DM;
            BAR_EXPECT(bfull + i * 8, BUFB);
            BULK_G2S(sbase + i * BUFB, src, BUFB, bfull + i * 8);
        }
    }

    const float4* t4 = (const float4*)(g_t + (size_t)b * DM);
    float4 tv[4];
    #pragma unroll
    for (int s = 0; s < 4; s++) tv[s] = t4[tid + 256 * s];

    float m = -INFINITY, l = 0.f;
    float4 A[4] = {{0,0,0,0},{0,0,0,0},{0,0,0,0},{0,0,0,0}};

    for (int base = 0; base < R; base += NBUF) {
        int g  = R - base; if (g > NBUF) g = NBUF;
        int u  = base / NBUF;
        uint32_t ph = u & 1;
        float* sr = sred + ph * (NBUF * 8);

        // phase 1: dots (buffers retained)
        for (int i = 0; i < g; i++) {
            bar_wait(bfull + i * 8, ph);
            float p = 0.f;
            #pragma unroll
            for (int s = 0; s < 4; s++)
                p += dot4(bufs[i * 1024 + tid + 256 * s], tv[s]);
            #pragma unroll
            for (int o = 16; o > 0; o >>= 1) p += __shfl_xor_sync(0xffffffffu, p, o);
            if (lane == 0) sr[i * 8 + wid] = p;
        }
        __syncthreads();

        // group softmax (all threads redundantly)
        float sc[NBUF];
        float mn = m;
        for (int i = 0; i < g; i++) {
            float s = 0.f;
            #pragma unroll
            for (int w = 0; w < 8; w++) s += sr[i * 8 + w];
            sc[i] = s;
            mn = fmaxf(mn, s);
        }
        float corr = __expf(m - mn);
        l *= corr;
        #pragma unroll
        for (int s = 0; s < 4; s++) {
            A[s].x *= corr; A[s].y *= corr; A[s].z *= corr; A[s].w *= corr;
        }

        // phase 2: accumulate from smem, release + refill each buffer
        for (int i = 0; i < g; i++) {
            float e = __expf(sc[i] - mn);
            l += e;
            #pragma unroll
            for (int s = 0; s < 4; s++)
                fma4(A[s], e, bufs[i * 1024 + tid + 256 * s]);
            BAR_ARRIVE(bempt + i * 8);
            if (tid == 0) {
                int nr = base + NBUF + i;
                if (nr < R) {
                    int s = r0 + nr;
                    const float* src = (s < SP) ? past + ((size_t)b * SP + s) * DM : x + (size_t)b * DM;
                    bar_wait(bempt + i * 8, ph);
                    BAR_EXPECT(bfull + i * 8, BUFB);
                    BULK_G2S(sbase + i * BUFB, src, BUFB, bfull + i * 8);
                }
            }
        }
        m = mn;
    }

    float4* acc4 = (float4*)(g_acc + ((size_t)b * NFB + cx) * DM);
    #pragma unroll
    for (int s = 0; s < 4; s++) acc4[tid + 256 * s] = A[s];
    if (tid == 0) { g_m[b * NFB + cx] = m; g_l[b * NFB + cx] = l; }
}

// ==================== combine 74 partials (+stats, Linv applied) ===========
__global__ __launch_bounds__(256) void k_combine() {
    int b   = blockIdx.y;
    int tid = threadIdx.x;
    __shared__ float smv[NFB], slv[NFB], swv[NFB];
    __shared__ float sM, sLinv;

    if (tid < NFB) { smv[tid] = g_m[b * NFB + tid]; slv[tid] = g_l[b * NFB + tid]; }
    __syncthreads();
    if (tid == 0) {
        float M = -INFINITY;
        for (int c = 0; c < NFB; c++) M = fmaxf(M, smv[c]);
        sM = M;
    }
    __syncthreads();
    if (tid < NFB) swv[tid] = __expf(smv[tid] - sM);
    __syncthreads();
    if (tid == 0) {
        float L = 0.f;
        for (int c = 0; c < NFB; c++) L += swv[c] * slv[c];
        sLinv = 1.f / L;
    }
    __syncthreads();

    int d = blockIdx.x * 256 + tid;
    const float* accp = g_acc + (size_t)b * NFB * DM + d;
    float s = 0.f;
    #pragma unroll 2
    for (int c = 0; c < NFB; c++) s += swv[c] * accp[(size_t)c * DM];
    g_p[b * DM + d] = s * sLinv;
}

// ==================== small forward gemv ====================
__global__ __launch_bounds__(256) void k_gemv4(
    const float* __restrict__ X, int xstride,
    const float* __restrict__ W, int ldw,
    float* __restrict__ Y, int ystride,
    int K, int N, int kchunk)
{
    const int N4 = N >> 2;
    const int ldw4 = ldw >> 2;
    int tid = threadIdx.x;
    int j4  = blockIdx.x * blockDim.x + tid;
    int d0  = blockIdx.y * kchunk;
    int d1  = min(K, d0 + kchunk);
    int nk  = d1 - d0;

    __shared__ float sx[BB][64];
    for (int i = tid; i < BB * nk; i += blockDim.x) {
        int bb = i / nk, kk = i - bb * nk;
        sx[bb][kk] = X[bb * xstride + d0 + kk];
    }
    __syncthreads();
    if (j4 >= N4) return;

    const float4* W4 = (const float4*)W;
    float4 a0 = {0,0,0,0}, a1 = a0, a2 = a0, a3 = a0;

    int k = 0;
    for (; k + 16 <= nk; k += 16) {
        float4 wv[16];
        #pragma unroll
        for (int i = 0; i < 16; i++)
            wv[i] = W4[(size_t)(d0 + k + i) * ldw4 + j4];
        #pragma unroll
        for (int i = 0; i < 16; i++) {
            fma4(a0, sx[0][k + i], wv[i]); fma4(a1, sx[1][k + i], wv[i]);
            fma4(a2, sx[2][k + i], wv[i]); fma4(a3, sx[3][k + i], wv[i]);
        }
    }
    for (; k < nk; k++) {
        float4 wv = W4[(size_t)(d0 + k) * ldw4 + j4];
        fma4(a0, sx[0][k], wv); fma4(a1, sx[1][k], wv);
        fma4(a2, sx[2][k], wv); fma4(a3, sx[3][k], wv);
    }

    int j = j4 * 4;
    atomicAdd(&Y[0 * ystride + j + 0], a0.x); atomicAdd(&Y[0 * ystride + j + 1], a0.y);
    atomicAdd(&Y[0 * ystride + j + 2], a0.z); atomicAdd(&Y[0 * ystride + j + 3], a0.w);
    atomicAdd(&Y[1 * ystride + j + 0], a1.x); atomicAdd(&Y[1 * ystride + j + 1], a1.y);
    atomicAdd(&Y[1 * ystride + j + 2], a1.z); atomicAdd(&Y[1 * ystride + j + 3], a1.w);
    atomicAdd(&Y[2 * ystride + j + 0], a2.x); atomicAdd(&Y[2 * ystride + j + 1], a2.y);
    atomicAdd(&Y[2 * ystride + j + 2], a2.z); atomicAdd(&Y[2 * ystride + j + 3], a2.w);
    atomicAdd(&Y[3 * ystride + j + 0], a3.x); atomicAdd(&Y[3 * ystride + j + 1], a3.y);
    atomicAdd(&Y[3 * ystride + j + 2], a3.z); atomicAdd(&Y[3 * ystride + j + 3], a3.w);
}

// ==================== small transposed gemv (step 7) ==============
__global__ __launch_bounds__(256) void k_gemv_t_s(
    const float* __restrict__ X, int xstride,
    const float* __restrict__ W, int ldw,
    float* __restrict__ Y, int ystride,
    int rows, int cols, float scalev)
{
    int gw   = (blockIdx.x * blockDim.x + threadIdx.x) >> 5;
    int lane = threadIdx.x & 31;
    if (gw >= rows) return;
    const float4* wp = (const float4*)(W + (size_t)gw * ldw);
    const float4* X4 = (const float4*)X;
    int cols4 = cols >> 2;
    int x4s   = xstride >> 2;

    float s0 = 0.f, s1 = 0.f, s2 = 0.f, s3 = 0.f;
    for (int c4 = lane; c4 < cols4; c4 += 32) {
        float4 wv = __ldg(&wp[c4]);
        s0 += dot4(wv, __ldg(&X4[0 * x4s + c4]));
        s1 += dot4(wv, __ldg(&X4[1 * x4s + c4]));
        s2 += dot4(wv, __ldg(&X4[2 * x4s + c4]));
        s3 += dot4(wv, __ldg(&X4[3 * x4s + c4]));
    }
    #pragma unroll
    for (int o = 16; o > 0; o >>= 1) {
        s0 += __shfl_xor_sync(0xffffffffu, s0, o);
        s1 += __shfl_xor_sync(0xffffffffu, s1, o);
        s2 += __shfl_xor_sync(0xffffffffu, s2, o);
        s3 += __shfl_xor_sync(0xffffffffu, s3, o);
    }
    if (lane == 0) {
        Y[0 * ystride + gw] = scalev * (Y[0 * ystride + gw] + s0);
        Y[1 * ystride + gw] = scalev * (Y[1 * ystride + gw] + s1);
        Y[2 * ystride + gw] = scalev * (Y[2 * ystride + gw] + s2);
        Y[3 * ystride + gw] = scalev * (Y[3 * ystride + gw] + s3);
    }
}

// ----------------------------------------------------------------------------
extern "C" void kernel_launch(void* const* d_in, const int* in_sizes, int n_in,
                              void* d_out, int out_size)
{
    const float* x    = (const float*)d_in[0];
    const float* past = (const float*)d_in[1];
    const float* Wdq  = (const float*)d_in[2];
    const float* Wuq  = (const float*)d_in[3];
    const float* Wqr  = (const float*)d_in[4];
    const float* Wdkv = (const float*)d_in[5];
    const float* Wkr  = (const float*)d_in[6];
    const float* F    = (const float*)d_in[7];
    const float* Wo   = (const float*)d_in[8];
    float* out = (float*)d_out;

    const float scale = 1.0f / sqrtf(2.0f * (float)DM);

    float *pCq, *pQc, *pQr, *pu, *pt, *pp, *pa, *pav;
    cudaGetSymbolAddress((void**)&pCq, g_Cq);
    cudaGetSymbolAddress((void**)&pQc, g_Qc);
    cudaGetSymbolAddress((void**)&pQr, g_Qr);
    cudaGetSymbolAddress((void**)&pu,  g_u);
    cudaGetSymbolAddress((void**)&pt,  g_t);
    cudaGetSymbolAddress((void**)&pp,  g_p);
    cudaGetSymbolAddress((void**)&pa,  g_a);
    cudaGetSymbolAddress((void**)&pav, g_av);

    const int FW_SMEM = NBUF * BUFB + 512 + 2 * NBUF * 8;
    const int TR_SMEM = NBUF * BUFB + 2 * NBUF * 8;
    const int FL_SMEM = NBUF * BUFB + 512 + 2 * NBUF * 8;
    cudaFuncSetAttribute(k_fw,    cudaFuncAttributeMaxDynamicSharedMemorySize, FW_SMEM);
    cudaFuncSetAttribute(k_tr,    cudaFuncAttributeMaxDynamicSharedMemorySize, TR_SMEM);
    cudaFuncSetAttribute(k_flash, cudaFuncAttributeMaxDynamicSharedMemorySize, FL_SMEM);

    // 1) zero atomic targets (incl. g_t, g_u for k_tr atomics)
    k_zero<<<128, 256>>>(out);

    // 2) Cq = x @ Wdq                   (64 MB, 296 blocks = 2/SM)
    k_fw<<<dim3(296, 1), 256, FW_SMEM>>>(x, Wdq, Wdq, pCq, pCq);
    // 3+4) Qc = Cq @ Wuq ; Qr = Cq @ Wqr (128 MB, 296 blocks)
    k_fw<<<dim3(148, 2), 256, FW_SMEM>>>(pCq, Wuq, Wqr, pQc, pQr);
    // 5) t += Wkr @ Qr                  (64 MB, sync-free)
    k_tr<<<296, 256, TR_SMEM>>>(pQr, Wkr, (size_t)DM, pt, DM, DM);
    // 6) u += F[:, :DM] @ Qc            (8 MB)
    k_tr<<<296, 256, TR_SMEM>>>(pQc, F, (size_t)(2 * DM), pu, LD, LD);
    // 7) t = scale * (t + Wdkv @ u)     (8 MB)
    k_gemv_t_s<<<512, 256>>>(pu, LD, Wdkv, LD, pt, DM, DM, LD, scale);

    // 8) flash v3 over [past_x; x]      (268 MB, persistent 296 blocks)
    k_flash<<<dim3(NFB, BB), 256, FL_SMEM>>>(x, past);
    // 9) combine 74 partials (+stats)   (4.9 MB)
    k_combine<<<dim3(16, BB), 256>>>();

    // 10) a = p @ Wdkv                  (8 MB)
    k_gemv4<<<dim3(1, 64), 256>>>(pp, DM, Wdkv, LD, pa, LD, DM, LD, 64);
    // 11) attn_v = a @ F[:, DM:]        (8 MB)
    k_gemv4<<<dim3(4, 8), 256>>>(pa, LD, F + DM, 2 * DM, pav, DM, LD, DM, 64);
    // 12) out = attn_v @ Wo             (64 MB)
    k_fw<<<dim3(296, 1), 256, FW_SMEM>>>(pav, Wo, Wo, out, out);
}

// round 10
// speedup vs baseline: 1.2118x; 1.2118x over previous
#include <cuda_runtime.h>
#include <math.h>
#include <stdint.h>

#define DM    4096
#define LD    512
#define BB    4
#define SP    4096
#define STOT  4097
#define NFB   74     /* flash blocks per batch */
#define BUFB  16384  /* one row: DM * 4 bytes */
#define NBUF  6      /* 96 KB ring -> 2 CTAs/SM */
#define NC    256    /* consumer threads */
#define THR   288    /* +1 producer warp */

// -------------------- device scratch --------------------
__device__ float g_Cq[BB * DM];
__device__ float g_Qc[BB * DM];
__device__ float g_Qr[BB * DM];
__device__ float g_u [BB * LD];
__device__ float g_t [BB * DM];
__device__ float g_m [BB * NFB];
__device__ float g_l [BB * NFB];
__device__ float g_acc[(size_t)BB * NFB * DM];   // 4.9 MB flash partials
__device__ float g_p [BB * DM];
__device__ float g_a [BB * LD];
__device__ float g_av[BB * DM];

// -------------------- ptx helpers --------------------
__device__ __forceinline__ uint32_t s2u(const void* p) {
    return (uint32_t)__cvta_generic_to_shared(p);
}
#define BAR_INIT(bar, cnt) \
    asm volatile("mbarrier.init.shared.b64 [%0], %1;" :: "r"(bar), "r"(cnt) : "memory")
#define BAR_EXPECT(bar, bytes) \
    asm volatile("mbarrier.arrive.expect_tx.shared.b64 _, [%0], %1;" :: "r"(bar), "r"(bytes) : "memory")
#define BAR_ARRIVE(bar) \
    asm volatile("mbarrier.arrive.shared.b64 _, [%0];" :: "r"(bar) : "memory")
#define BULK_G2S(dst, src, bytes, bar) \
    asm volatile("cp.async.bulk.shared::cluster.global.mbarrier::complete_tx::bytes [%0], [%1], %2, [%3];" \
                 :: "r"(dst), "l"(src), "r"(bytes), "r"(bar) : "memory")
#define FENCE_ASYNC() \
    asm volatile("fence.proxy.async.shared::cta;" ::: "memory")
#define CBAR() \
    asm volatile("bar.sync 1, 256;" ::: "memory")   /* consumer-only barrier */

__device__ __forceinline__ void bar_wait(uint32_t bar, uint32_t parity) {
    asm volatile(
        "{\n\t.reg .pred P;\n"
        "LW_%=:\n\t"
        "mbarrier.try_wait.parity.shared.b64 P, [%0], %1, 0x989680;\n\t"
        "@P bra LD_%=;\n\t"
        "bra LW_%=;\n"
        "LD_%=:\n\t}"
        :: "r"(bar), "r"(parity) : "memory");
}

__device__ __forceinline__ void fma4(float4& a, float s, const float4& v) {
    a.x += s * v.x; a.y += s * v.y; a.z += s * v.z; a.w += s * v.w;
}
__device__ __forceinline__ float dot4(const float4& a, const float4& b) {
    return a.x * b.x + a.y * b.y + a.z * b.z + a.w * b.w;
}

// -------------------- zero atomic targets --------------------
__global__ void k_zero(float* __restrict__ out) {
    int i = blockIdx.x * blockDim.x + threadIdx.x;
    int stride = gridDim.x * blockDim.x;
    for (int j = i; j < BB * DM; j += stride) {
        g_Cq[j] = 0.f; g_Qc[j] = 0.f; g_Qr[j] = 0.f;
        g_t[j] = 0.f; g_av[j] = 0.f; out[j] = 0.f;
    }
    for (int j = i; j < BB * LD; j += stride) { g_a[j] = 0.f; g_u[j] = 0.f; }
}

// ==================== producer helper: per-buffer refill loop ==============
__device__ __forceinline__ void produce_rows(
    int pl, int R, const float* W, size_t ldw, int r0,
    uint32_t sbase, uint32_t bfull, uint32_t bempt)
{
    uint32_t php = 1;   // first empty-wait passes on a fresh barrier
    for (int rr = pl; rr < R; rr += NBUF) {
        bar_wait(bempt + pl * 8, php);
        BAR_EXPECT(bfull + pl * 8, BUFB);
        BULK_G2S(sbase + pl * BUFB, W + (size_t)(r0 + rr) * ldw, BUFB, bfull + pl * 8);
        php ^= 1;
    }
}

// ==================== warp-specialized forward gemv ====================
// Y[b][:] += X[b][:] @ W; 6x16KB ring; warp 8 = producer, warps 0-7 consume.
__global__ __launch_bounds__(THR) void k_fw(
    const float* __restrict__ X,
    const float* __restrict__ W0, const float* __restrict__ W1,
    float* __restrict__ Y0, float* __restrict__ Y1)
{
    const float* W = blockIdx.y ? W1 : W0;
    float*       Y = blockIdx.y ? Y1 : Y0;
    extern __shared__ __align__(16) unsigned char sm[];
    float4* bufs = (float4*)sm;
    float*  sxv  = (float*)(sm + NBUF * BUFB);        // [BB][32]
    uint32_t sbase = s2u(sm);
    uint32_t bfull = sbase + NBUF * BUFB + 512;
    uint32_t bempt = bfull + 64;
    int tid = threadIdx.x;

    int r0 = (int)(((long long)blockIdx.x * DM) / gridDim.x);
    int r1 = (int)(((long long)(blockIdx.x + 1) * DM) / gridDim.x);
    int R  = r1 - r0;

    if (tid == 0) {
        #pragma unroll
        for (int i = 0; i < NBUF; i++) { BAR_INIT(bfull + i * 8, 1); BAR_INIT(bempt + i * 8, NC); }
    }
    if (tid < NC) {
        for (int i = tid; i < BB * R; i += NC) {
            int bb = i / R, rr = i - bb * R;
            sxv[bb * 32 + rr] = X[bb * DM + r0 + rr];
        }
    }
    __syncthreads();
    FENCE_ASYNC();

    if (tid >= NC) {                       // producer warp
        int pl = tid - NC;
        if (pl < NBUF) produce_rows(pl, R, W, DM, r0, sbase, bfull, bempt);
        return;
    }

    float4 a0[4] = {{0,0,0,0},{0,0,0,0},{0,0,0,0},{0,0,0,0}};
    float4 a1[4] = {{0,0,0,0},{0,0,0,0},{0,0,0,0},{0,0,0,0}};
    float4 a2[4] = {{0,0,0,0},{0,0,0,0},{0,0,0,0},{0,0,0,0}};
    float4 a3[4] = {{0,0,0,0},{0,0,0,0},{0,0,0,0},{0,0,0,0}};

    int buf = 0; uint32_t ph = 0;
    for (int rr = 0; rr < R; rr++) {
        bar_wait(bfull + buf * 8, ph);
        float x0 = sxv[0 * 32 + rr], x1 = sxv[1 * 32 + rr];
        float x2 = sxv[2 * 32 + rr], x3 = sxv[3 * 32 + rr];
        #pragma unroll
        for (int s = 0; s < 4; s++) {
            float4 wv = bufs[buf * 1024 + tid + 256 * s];
            fma4(a0[s], x0, wv); fma4(a1[s], x1, wv);
            fma4(a2[s], x2, wv); fma4(a3[s], x3, wv);
        }
        BAR_ARRIVE(bempt + buf * 8);
        if (++buf == NBUF) { buf = 0; ph ^= 1; }
    }

    #pragma unroll
    for (int s = 0; s < 4; s++) {
        int j = (tid + 256 * s) * 4;
        atomicAdd(&Y[0 * DM + j + 0], a0[s].x); atomicAdd(&Y[0 * DM + j + 1], a0[s].y);
        atomicAdd(&Y[0 * DM + j + 2], a0[s].z); atomicAdd(&Y[0 * DM + j + 3], a0[s].w);
        atomicAdd(&Y[1 * DM + j + 0], a1[s].x); atomicAdd(&Y[1 * DM + j + 1], a1[s].y);
        atomicAdd(&Y[1 * DM + j + 2], a1[s].z); atomicAdd(&Y[1 * DM + j + 3], a1[s].w);
        atomicAdd(&Y[2 * DM + j + 0], a2[s].x); atomicAdd(&Y[2 * DM + j + 1], a2[s].y);
        atomicAdd(&Y[2 * DM + j + 2], a2[s].z); atomicAdd(&Y[2 * DM + j + 3], a2[s].w);
        atomicAdd(&Y[3 * DM + j + 0], a3[s].x); atomicAdd(&Y[3 * DM + j + 1], a3[s].y);
        atomicAdd(&Y[3 * DM + j + 2], a3[s].z); atomicAdd(&Y[3 * DM + j + 3], a3[s].w);
    }
}

// ==================== warp-specialized transposed gemv =====================
// Y[b][r] += dot(W[r][:DM], Q[b][:]). Y pre-zeroed; lane-0 atomics.
__global__ __launch_bounds__(THR) void k_tr(
    const float* __restrict__ Q,
    const float* __restrict__ W, size_t ldw,
    float* __restrict__ Y, int ystride, int rows)
{
    extern __shared__ __align__(16) unsigned char sm[];
    float4* bufs = (float4*)sm;
    uint32_t sbase = s2u(sm);
    uint32_t bfull = sbase + NBUF * BUFB;
    uint32_t bempt = bfull + 64;
    int tid  = threadIdx.x;
    int lane = tid & 31;

    int r0 = (int)(((long long)blockIdx.x * rows) / gridDim.x);
    int r1 = (int)(((long long)(blockIdx.x + 1) * rows) / gridDim.x);
    int R  = r1 - r0;

    if (tid == 0) {
        #pragma unroll
        for (int i = 0; i < NBUF; i++) { BAR_INIT(bfull + i * 8, 1); BAR_INIT(bempt + i * 8, NC); }
    }
    __syncthreads();
    FENCE_ASYNC();

    if (tid >= NC) {
        int pl = tid - NC;
        if (pl < NBUF) produce_rows(pl, R, W, ldw, r0, sbase, bfull, bempt);
        return;
    }

    const float4* Q4 = (const float4*)Q;
    float4 q[BB][4];
    #pragma unroll
    for (int b = 0; b < BB; b++)
        #pragma unroll
        for (int s = 0; s < 4; s++)
            q[b][s] = Q4[b * 1024 + tid + 256 * s];

    int buf = 0; uint32_t ph = 0;
    for (int rr = 0; rr < R; rr++) {
        bar_wait(bfull + buf * 8, ph);
        float p0 = 0.f, p1 = 0.f, p2 = 0.f, p3 = 0.f;
        #pragma unroll
        for (int s = 0; s < 4; s++) {
            float4 wv = bufs[buf * 1024 + tid + 256 * s];
            p0 += dot4(wv, q[0][s]); p1 += dot4(wv, q[1][s]);
            p2 += dot4(wv, q[2][s]); p3 += dot4(wv, q[3][s]);
        }
        BAR_ARRIVE(bempt + buf * 8);
        #pragma unroll
        for (int o = 16; o > 0; o >>= 1) {
            p0 += __shfl_xor_sync(0xffffffffu, p0, o);
            p1 += __shfl_xor_sync(0xffffffffu, p1, o);
            p2 += __shfl_xor_sync(0xffffffffu, p2, o);
            p3 += __shfl_xor_sync(0xffffffffu, p3, o);
        }
        if (lane == 0) {
            atomicAdd(&Y[0 * ystride + r0 + rr], p0);
            atomicAdd(&Y[1 * ystride + r0 + rr], p1);
            atomicAdd(&Y[2 * ystride + r0 + rr], p2);
            atomicAdd(&Y[3 * ystride + r0 + rr], p3);
        }
        if (++buf == NBUF) { buf = 0; ph ^= 1; }
    }
}

// ==================== flash: persistent ring + per-row online softmax ======
__global__ __launch_bounds__(THR) void k_flash(
    const float* __restrict__ x, const float* __restrict__ past)
{
    int b    = blockIdx.y;
    int cx   = blockIdx.x;
    int tid  = threadIdx.x;
    int wid  = tid >> 5;
    int lane = tid & 31;
    extern __shared__ __align__(16) unsigned char sm[];
    float4* bufs = (float4*)sm;
    float*  sred = (float*)(sm + NBUF * BUFB);        // [2][8]
    uint32_t sbase = s2u(sm);
    uint32_t bfull = sbase + NBUF * BUFB + 64;
    uint32_t bempt = bfull + 64;

    int r0 = (int)(((long long)cx * STOT) / NFB);
    int r1 = (int)(((long long)(cx + 1) * STOT) / NFB);
    int R  = r1 - r0;

    if (tid == 0) {
        #pragma unroll
        for (int i = 0; i < NBUF; i++) { BAR_INIT(bfull + i * 8, 1); BAR_INIT(bempt + i * 8, NC); }
    }
    __syncthreads();
    FENCE_ASYNC();

    if (tid >= NC) {                       // producer warp: per-row src select
        int pl = tid - NC;
        if (pl < NBUF) {
            uint32_t php = 1;
            for (int rr = pl; rr < R; rr += NBUF) {
                int s = r0 + rr;
                const float* src = (s < SP) ? past + ((size_t)b * SP + s) * DM
                                            : x + (size_t)b * DM;
                bar_wait(bempt + pl * 8, php);
                BAR_EXPECT(bfull + pl * 8, BUFB);
                BULK_G2S(sbase + pl * BUFB, src, BUFB, bfull + pl * 8);
                php ^= 1;
            }
        }
        return;
    }

    const float4* t4 = (const float4*)(g_t + (size_t)b * DM);
    float4 tv[4];
    #pragma unroll
    for (int s = 0; s < 4; s++) tv[s] = t4[tid + 256 * s];

    float m = -INFINITY, l = 0.f;
    float4 A[4] = {{0,0,0,0},{0,0,0,0},{0,0,0,0},{0,0,0,0}};

    int buf = 0; uint32_t ph = 0;
    for (int rr = 0; rr < R; rr++) {
        bar_wait(bfull + buf * 8, ph);
        float4 v[4];
        #pragma unroll
        for (int s = 0; s < 4; s++) v[s] = bufs[buf * 1024 + tid + 256 * s];

        float p = dot4(v[0], tv[0]) + dot4(v[1], tv[1])
                + dot4(v[2], tv[2]) + dot4(v[3], tv[3]);
        #pragma unroll
        for (int o = 16; o > 0; o >>= 1) p += __shfl_xor_sync(0xffffffffu, p, o);
        if (lane == 0) sred[(rr & 1) * 8 + wid] = p;
        CBAR();
        const float* sr = sred + (rr & 1) * 8;
        float score = sr[0] + sr[1] + sr[2] + sr[3] + sr[4] + sr[5] + sr[6] + sr[7];

        float mn   = fmaxf(m, score);
        float corr = __expf(m - mn);
        float e    = __expf(score - mn);
        l = l * corr + e;
        #pragma unroll
        for (int s = 0; s < 4; s++) {
            A[s].x = A[s].x * corr + e * v[s].x;
            A[s].y = A[s].y * corr + e * v[s].y;
            A[s].z = A[s].z * corr + e * v[s].z;
            A[s].w = A[s].w * corr + e * v[s].w;
        }
        m = mn;
        BAR_ARRIVE(bempt + buf * 8);
        if (++buf == NBUF) { buf = 0; ph ^= 1; }
    }

    float4* acc4 = (float4*)(g_acc + ((size_t)b * NFB + cx) * DM);
    #pragma unroll
    for (int s = 0; s < 4; s++) acc4[tid + 256 * s] = A[s];
    if (tid == 0) { g_m[b * NFB + cx] = m; g_l[b * NFB + cx] = l; }
}

// ==================== combine 74 partials (+stats, Linv applied) ===========
__global__ __launch_bounds__(256) void k_combine() {
    int b   = blockIdx.y;
    int tid = threadIdx.x;
    __shared__ float smv[NFB], slv[NFB], swv[NFB];
    __shared__ float sM, sLinv;

    if (tid < NFB) { smv[tid] = g_m[b * NFB + tid]; slv[tid] = g_l[b * NFB + tid]; }
    __syncthreads();
    if (tid == 0) {
        float M = -INFINITY;
        for (int c = 0; c < NFB; c++) M = fmaxf(M, smv[c]);
        sM = M;
    }
    __syncthreads();
    if (tid < NFB) swv[tid] = __expf(smv[tid] - sM);
    __syncthreads();
    if (tid == 0) {
        float L = 0.f;
        for (int c = 0; c < NFB; c++) L += swv[c] * slv[c];
        sLinv = 1.f / L;
    }
    __syncthreads();

    int d = blockIdx.x * 256 + tid;
    const float* accp = g_acc + (size_t)b * NFB * DM + d;
    float s = 0.f;
    #pragma unroll 2
    for (int c = 0; c < NFB; c++) s += swv[c] * accp[(size_t)c * DM];
    g_p[b * DM + d] = s * sLinv;
}

// ==================== small forward gemv ====================
__global__ __launch_bounds__(256) void k_gemv4(
    const float* __restrict__ X, int xstride,
    const float* __restrict__ W, int ldw,
    float* __restrict__ Y, int ystride,
    int K, int N, int kchunk)
{
    const int N4 = N >> 2;
    const int ldw4 = ldw >> 2;
    int tid = threadIdx.x;
    int j4  = blockIdx.x * blockDim.x + tid;
    int d0  = blockIdx.y * kchunk;
    int d1  = min(K, d0 + kchunk);
    int nk  = d1 - d0;

    __shared__ float sx[BB][64];
    for (int i = tid; i < BB * nk; i += blockDim.x) {
        int bb = i / nk, kk = i - bb * nk;
        sx[bb][kk] = X[bb * xstride + d0 + kk];
    }
    __syncthreads();
    if (j4 >= N4) return;

    const float4* W4 = (const float4*)W;
    float4 a0 = {0,0,0,0}, a1 = a0, a2 = a0, a3 = a0;

    int k = 0;
    for (; k + 16 <= nk; k += 16) {
        float4 wv[16];
        #pragma unroll
        for (int i = 0; i < 16; i++)
            wv[i] = W4[(size_t)(d0 + k + i) * ldw4 + j4];
        #pragma unroll
        for (int i = 0; i < 16; i++) {
            fma4(a0, sx[0][k + i], wv[i]); fma4(a1, sx[1][k + i], wv[i]);
            fma4(a2, sx[2][k + i], wv[i]); fma4(a3, sx[3][k + i], wv[i]);
        }
    }
    for (; k < nk; k++) {
        float4 wv = W4[(size_t)(d0 + k) * ldw4 + j4];
        fma4(a0, sx[0][k], wv); fma4(a1, sx[1][k], wv);
        fma4(a2, sx[2][k], wv); fma4(a3, sx[3][k], wv);
    }

    int j = j4 * 4;
    atomicAdd(&Y[0 * ystride + j + 0], a0.x); atomicAdd(&Y[0 * ystride + j + 1], a0.y);
    atomicAdd(&Y[0 * ystride + j + 2], a0.z); atomicAdd(&Y[0 * ystride + j + 3], a0.w);
    atomicAdd(&Y[1 * ystride + j + 0], a1.x); atomicAdd(&Y[1 * ystride + j + 1], a1.y);
    atomicAdd(&Y[1 * ystride + j + 2], a1.z); atomicAdd(&Y[1 * ystride + j + 3], a1.w);
    atomicAdd(&Y[2 * ystride + j + 0], a2.x); atomicAdd(&Y[2 * ystride + j + 1], a2.y);
    atomicAdd(&Y[2 * ystride + j + 2], a2.z); atomicAdd(&Y[2 * ystride + j + 3], a2.w);
    atomicAdd(&Y[3 * ystride + j + 0], a3.x); atomicAdd(&Y[3 * ystride + j + 1], a3.y);
    atomicAdd(&Y[3 * ystride + j + 2], a3.z); atomicAdd(&Y[3 * ystride + j + 3], a3.w);
}

// ==================== small transposed gemv (step 7) ==============
__global__ __launch_bounds__(256) void k_gemv_t_s(
    const float* __restrict__ X, int xstride,
    const float* __restrict__ W, int ldw,
    float* __restrict__ Y, int ystride,
    int rows, int cols, float scalev)
{
    int gw   = (blockIdx.x * blockDim.x + threadIdx.x) >> 5;
    int lane = threadIdx.x & 31;
    if (gw >= rows) return;
    const float4* wp = (const float4*)(W + (size_t)gw * ldw);
    const float4* X4 = (const float4*)X;
    int cols4 = cols >> 2;
    int x4s   = xstride >> 2;

    float s0 = 0.f, s1 = 0.f, s2 = 0.f, s3 = 0.f;
    for (int c4 = lane; c4 < cols4; c4 += 32) {
        float4 wv = __ldg(&wp[c4]);
        s0 += dot4(wv, __ldg(&X4[0 * x4s + c4]));
        s1 += dot4(wv, __ldg(&X4[1 * x4s + c4]));
        s2 += dot4(wv, __ldg(&X4[2 * x4s + c4]));
        s3 += dot4(wv, __ldg(&X4[3 * x4s + c4]));
    }
    #pragma unroll
    for (int o = 16; o > 0; o >>= 1) {
        s0 += __shfl_xor_sync(0xffffffffu, s0, o);
        s1 += __shfl_xor_sync(0xffffffffu, s1, o);
        s2 += __shfl_xor_sync(0xffffffffu, s2, o);
        s3 += __shfl_xor_sync(0xffffffffu, s3, o);
    }
    if (lane == 0) {
        Y[0 * ystride + gw] = scalev * (Y[0 * ystride + gw] + s0);
        Y[1 * ystride + gw] = scalev * (Y[1 * ystride + gw] + s1);
        Y[2 * ystride + gw] = scalev * (Y[2 * ystride + gw] + s2);
        Y[3 * ystride + gw] = scalev * (Y[3 * ystride + gw] + s3);
    }
}

// ----------------------------------------------------------------------------
extern "C" void kernel_launch(void* const* d_in, const int* in_sizes, int n_in,
                              void* d_out, int out_size)
{
    const float* x    = (const float*)d_in[0];
    const float* past = (const float*)d_in[1];
    const float* Wdq  = (const float*)d_in[2];
    const float* Wuq  = (const float*)d_in[3];
    const float* Wqr  = (const float*)d_in[4];
    const float* Wdkv = (const float*)d_in[5];
    const float* Wkr  = (const float*)d_in[6];
    const float* F    = (const float*)d_in[7];
    const float* Wo   = (const float*)d_in[8];
    float* out = (float*)d_out;

    const float scale = 1.0f / sqrtf(2.0f * (float)DM);

    float *pCq, *pQc, *pQr, *pu, *pt, *pp, *pa, *pav;
    cudaGetSymbolAddress((void**)&pCq, g_Cq);
    cudaGetSymbolAddress((void**)&pQc, g_Qc);
    cudaGetSymbolAddress((void**)&pQr, g_Qr);
    cudaGetSymbolAddress((void**)&pu,  g_u);
    cudaGetSymbolAddress((void**)&pt,  g_t);
    cudaGetSymbolAddress((void**)&pp,  g_p);
    cudaGetSymbolAddress((void**)&pa,  g_a);
    cudaGetSymbolAddress((void**)&pav, g_av);

    const int FW_SMEM = NBUF * BUFB + 512 + 128;
    const int TR_SMEM = NBUF * BUFB + 128;
    const int FL_SMEM = NBUF * BUFB + 64 + 128;
    cudaFuncSetAttribute(k_fw,    cudaFuncAttributeMaxDynamicSharedMemorySize, FW_SMEM);
    cudaFuncSetAttribute(k_tr,    cudaFuncAttributeMaxDynamicSharedMemorySize, TR_SMEM);
    cudaFuncSetAttribute(k_flash, cudaFuncAttributeMaxDynamicSharedMemorySize, FL_SMEM);

    // 1) zero atomic targets
    k_zero<<<128, 256>>>(out);

    // 2) Cq = x @ Wdq                   (64 MB)
    k_fw<<<dim3(296, 1), THR, FW_SMEM>>>(x, Wdq, Wdq, pCq, pCq);
    // 3+4) Qc = Cq @ Wuq ; Qr = Cq @ Wqr (128 MB)
    k_fw<<<dim3(148, 2), THR, FW_SMEM>>>(pCq, Wuq, Wqr, pQc, pQr);
    // 5) t += Wkr @ Qr                  (64 MB)
    k_tr<<<296, THR, TR_SMEM>>>(pQr, Wkr, (size_t)DM, pt, DM, DM);
    // 6) u += F[:, :DM] @ Qc            (8 MB)
    k_tr<<<128, THR, TR_SMEM>>>(pQc, F, (size_t)(2 * DM), pu, LD, LD);
    // 7) t = scale * (t + Wdkv @ u)     (8 MB)
    k_gemv_t_s<<<512, 256>>>(pu, LD, Wdkv, LD, pt, DM, DM, LD, scale);

    // 8) flash over [past_x; x]         (268 MB, persistent ring)
    k_flash<<<dim3(NFB, BB), THR, FL_SMEM>>>(x, past);
    // 9) combine 74 partials (+stats)   (4.9 MB)
    k_combine<<<dim3(16, BB), 256>>>();

    // 10) a = p @ Wdkv                  (8 MB)
    k_gemv4<<<dim3(1, 64), 256>>>(pp, DM, Wdkv, LD, pa, LD, DM, LD, 64);
    // 11) attn_v = a @ F[:, DM:]        (8 MB)
    k_gemv4<<<dim3(4, 8), 256>>>(pa, LD, F + DM, 2 * DM, pav, DM, LD, DM, 64);
    // 12) out = attn_v @ Wo             (64 MB)
    k_fw<<<dim3(296, 1), THR, FW_SMEM>>>(pav, Wo, Wo, out, out);
}

// round 11
// speedup vs baseline: 1.7031x; 1.4055x over previous
#include <cuda_runtime.h>
#include <math.h>
#include <stdint.h>

#define DM    4096
#define LD    512
#define BB    4
#define SP    4096
#define STOT  4097
#define NFB   74     /* flash blocks per batch */
#define BUFB  16384  /* one row: DM * 4 bytes */
#define NBUF  6      /* flash ring: 6 x 16 KB */
#define NC    256    /* consumer threads */
#define THR   288    /* +1 producer warp */

/* k_fw v2 geometry */
#define FWK   37     /* k slices */
#define FWC   8      /* column slices */
#define CSL   512    /* columns per CTA */
#define CSLB  2048   /* bytes of one row window */
#define KBR   16     /* k-rows per buffer */
#define FWNB  3      /* fw ring depth (3 x 32 KB) */
#define FWBUF 32768

/* k_tr v2 geometry */
#define TRNB  3      /* 3 x 32 KB (2 rows each) */

// -------------------- device scratch --------------------
__device__ float g_Cq[BB * DM];
__device__ float g_Qc[BB * DM];
__device__ float g_Qr[BB * DM];
__device__ float g_u [BB * LD];
__device__ float g_t [BB * DM];
__device__ float g_m [BB * NFB];
__device__ float g_l [BB * NFB];
__device__ float g_acc[(size_t)BB * NFB * DM];
__device__ float g_p [BB * DM];
__device__ float g_a [BB * LD];
__device__ float g_av[BB * DM];

// -------------------- ptx helpers --------------------
__device__ __forceinline__ uint32_t s2u(const void* p) {
    return (uint32_t)__cvta_generic_to_shared(p);
}
#define BAR_INIT(bar, cnt) \
    asm volatile("mbarrier.init.shared.b64 [%0], %1;" :: "r"(bar), "r"(cnt) : "memory")
#define BAR_EXPECT(bar, bytes) \
    asm volatile("mbarrier.arrive.expect_tx.shared.b64 _, [%0], %1;" :: "r"(bar), "r"(bytes) : "memory")
#define BAR_ARRIVE(bar) \
    asm volatile("mbarrier.arrive.shared.b64 _, [%0];" :: "r"(bar) : "memory")
#define BULK_G2S(dst, src, bytes, bar) \
    asm volatile("cp.async.bulk.shared::cluster.global.mbarrier::complete_tx::bytes [%0], [%1], %2, [%3];" \
                 :: "r"(dst), "l"(src), "r"(bytes), "r"(bar) : "memory")
#define FENCE_ASYNC() \
    asm volatile("fence.proxy.async.shared::cta;" ::: "memory")
#define CBAR() \
    asm volatile("bar.sync 1, 256;" ::: "memory")

__device__ __forceinline__ void bar_wait(uint32_t bar, uint32_t parity) {
    asm volatile(
        "{\n\t.reg .pred P;\n"
        "LW_%=:\n\t"
        "mbarrier.try_wait.parity.shared.b64 P, [%0], %1, 0x989680;\n\t"
        "@P bra LD_%=;\n\t"
        "bra LW_%=;\n"
        "LD_%=:\n\t}"
        :: "r"(bar), "r"(parity) : "memory");
}

__device__ __forceinline__ void fma4(float4& a, float s, const float4& v) {
    a.x += s * v.x; a.y += s * v.y; a.z += s * v.z; a.w += s * v.w;
}
__device__ __forceinline__ float dot4(const float4& a, const float4& b) {
    return a.x * b.x + a.y * b.y + a.z * b.z + a.w * b.w;
}

// -------------------- zero atomic targets --------------------
__global__ void k_zero(float* __restrict__ out) {
    int i = blockIdx.x * blockDim.x + threadIdx.x;
    int stride = gridDim.x * blockDim.x;
    for (int j = i; j < BB * DM; j += stride) {
        g_Cq[j] = 0.f; g_Qc[j] = 0.f; g_Qr[j] = 0.f;
        g_t[j] = 0.f; g_av[j] = 0.f; out[j] = 0.f;
    }
    for (int j = i; j < BB * LD; j += stride) { g_a[j] = 0.f; g_u[j] = 0.f; }
}

// ==================== k_fw v2: column-split streaming gemv ==================
// Y[b][c0:c0+512] += sum over k-slice of X[b][k] * W[k][c0:c0+512]
// grid (FWK, FWC, nmat); 37 CTAs contribute per output (8x fewer atomics).
__global__ __launch_bounds__(THR) void k_fw(
    const float* __restrict__ X,
    const float* __restrict__ W0, const float* __restrict__ W1,
    float* __restrict__ Y0, float* __restrict__ Y1)
{
    const float* W = blockIdx.z ? W1 : W0;
    float*       Y = blockIdx.z ? Y1 : Y0;
    extern __shared__ __align__(16) unsigned char sm[];
    float*  sxv  = (float*)(sm + FWNB * FWBUF);       // [128][4] interleaved x
    uint32_t sbase = s2u(sm);
    uint32_t bfull = sbase + FWNB * FWBUF + 2048;
    uint32_t bempt = bfull + 32;
    int tid = threadIdx.x;

    int c0 = blockIdx.y * CSL;
    int k0 = (int)(((long long)blockIdx.x * DM) / FWK);
    int k1 = (int)(((long long)(blockIdx.x + 1) * DM) / FWK);
    int R  = k1 - k0;
    int nch = (R + KBR - 1) / KBR;

    if (tid == 0) {
        #pragma unroll
        for (int i = 0; i < FWNB; i++) { BAR_INIT(bfull + i * 8, 1); BAR_INIT(bempt + i * 8, NC); }
    }
    if (tid < NC) {
        for (int i = tid; i < R; i += NC) {
            float4 xv = { X[0 * DM + k0 + i], X[1 * DM + k0 + i],
                          X[2 * DM + k0 + i], X[3 * DM + k0 + i] };
            ((float4*)sxv)[i] = xv;
        }
    }
    __syncthreads();
    FENCE_ASYNC();

    if (tid >= NC) {                       // producer warp: lanes 0..2
        int pl = tid - NC;
        if (pl < FWNB) {
            uint32_t php = 1;
            for (int j = pl; j < nch; j += FWNB) {
                int rb = j * KBR;
                int nr = R - rb; if (nr > KBR) nr = KBR;
                bar_wait(bempt + pl * 8, php);
                BAR_EXPECT(bfull + pl * 8, (uint32_t)(nr * CSLB));
                for (int i = 0; i < nr; i++)
                    BULK_G2S(sbase + pl * FWBUF + i * CSLB,
                             W + (size_t)(k0 + rb + i) * DM + c0, CSLB, bfull + pl * 8);
                php ^= 1;
            }
        }
        return;
    }

    // consumer: thread owns columns c0+2*tid, c0+2*tid+1; 8 accumulators
    float2 acc[BB] = {{0,0},{0,0},{0,0},{0,0}};

    int buf = 0; uint32_t ph = 0;
    for (int j = 0; j < nch; j++) {
        int rb = j * KBR;
        int nr = R - rb; if (nr > KBR) nr = KBR;
        bar_wait(bfull + buf * 8, ph);
        const float2* wrow = (const float2*)(sm + buf * FWBUF);
        if (nr == KBR) {
            #pragma unroll
            for (int r = 0; r < KBR; r++) {
                float2 wv = wrow[r * 256 + tid];
                float4 xv = ((const float4*)sxv)[rb + r];
                acc[0].x += xv.x * wv.x; acc[0].y += xv.x * wv.y;
                acc[1].x += xv.y * wv.x; acc[1].y += xv.y * wv.y;
                acc[2].x += xv.z * wv.x; acc[2].y += xv.z * wv.y;
                acc[3].x += xv.w * wv.x; acc[3].y += xv.w * wv.y;
            }
        } else {
            for (int r = 0; r < nr; r++) {
                float2 wv = wrow[r * 256 + tid];
                float4 xv = ((const float4*)sxv)[rb + r];
                acc[0].x += xv.x * wv.x; acc[0].y += xv.x * wv.y;
                acc[1].x += xv.y * wv.x; acc[1].y += xv.y * wv.y;
                acc[2].x += xv.z * wv.x; acc[2].y += xv.z * wv.y;
                acc[3].x += xv.w * wv.x; acc[3].y += xv.w * wv.y;
            }
        }
        BAR_ARRIVE(bempt + buf * 8);
        if (++buf == FWNB) { buf = 0; ph ^= 1; }
    }

    int c = c0 + 2 * tid;
    #pragma unroll
    for (int b = 0; b < BB; b++) {
        atomicAdd(&Y[b * DM + c + 0], acc[b].x);
        atomicAdd(&Y[b * DM + c + 1], acc[b].y);
    }
}

// ==================== k_tr v2: 2-row chunks, merged dual-job ================
// Y[b][r] += dot(W[r][:DM], Q[b][:]). Y pre-zeroed.
__global__ __launch_bounds__(THR) void k_tr(
    const float* __restrict__ Q0, const float* __restrict__ W0, size_t ldw0,
    float* __restrict__ Y0c, int ys0, int rows0, int nblk0,
    const float* __restrict__ Q1, const float* __restrict__ W1, size_t ldw1,
    float* __restrict__ Y1c, int ys1, int rows1, int nblk1)
{
    const float* Q; const float* W; size_t ldw; float* Y; int ys, rows, bx, nblk;
    if ((int)blockIdx.x < nblk0) {
        Q = Q0; W = W0; ldw = ldw0; Y = Y0c; ys = ys0; rows = rows0;
        bx = blockIdx.x; nblk = nblk0;
    } else {
        Q = Q1; W = W1; ldw = ldw1; Y = Y1c; ys = ys1; rows = rows1;
        bx = blockIdx.x - nblk0; nblk = nblk1;
    }
    extern __shared__ __align__(16) unsigned char sm[];
    uint32_t sbase = s2u(sm);
    uint32_t bfull = sbase + TRNB * FWBUF;
    uint32_t bempt = bfull + 32;
    int tid  = threadIdx.x;
    int lane = tid & 31;

    int r0 = (int)(((long long)bx * rows) / nblk);
    int r1 = (int)(((long long)(bx + 1) * rows) / nblk);
    int R  = r1 - r0;
    int nch = (R + 1) / 2;

    if (tid == 0) {
        #pragma unroll
        for (int i = 0; i < TRNB; i++) { BAR_INIT(bfull + i * 8, 1); BAR_INIT(bempt + i * 8, NC); }
    }
    __syncthreads();
    FENCE_ASYNC();

    if (tid >= NC) {
        int pl = tid - NC;
        if (pl < TRNB) {
            uint32_t php = 1;
            for (int j = pl; j < nch; j += TRNB) {
                int rb = 2 * j;
                int nr = R - rb; if (nr > 2) nr = 2;
                bar_wait(bempt + pl * 8, php);
                BAR_EXPECT(bfull + pl * 8, (uint32_t)(nr * BUFB));
                for (int i = 0; i < nr; i++)
                    BULK_G2S(sbase + pl * FWBUF + i * BUFB,
                             W + (size_t)(r0 + rb + i) * ldw, BUFB, bfull + pl * 8);
                php ^= 1;
            }
        }
        return;
    }

    const float4* Q4 = (const float4*)Q;
    float4 q[BB][4];
    #pragma unroll
    for (int b = 0; b < BB; b++)
        #pragma unroll
        for (int s = 0; s < 4; s++)
            q[b][s] = Q4[b * 1024 + tid + 256 * s];

    int buf = 0; uint32_t ph = 0;
    for (int j = 0; j < nch; j++) {
        int rb = 2 * j;
        int nr = R - rb; if (nr > 2) nr = 2;
        bar_wait(bfull + buf * 8, ph);
        for (int i = 0; i < nr; i++) {
            const float4* bufr = (const float4*)(sm + buf * FWBUF + i * BUFB);
            float p0 = 0.f, p1 = 0.f, p2 = 0.f, p3 = 0.f;
            #pragma unroll
            for (int s = 0; s < 4; s++) {
                float4 wv = bufr[tid + 256 * s];
                p0 += dot4(wv, q[0][s]); p1 += dot4(wv, q[1][s]);
                p2 += dot4(wv, q[2][s]); p3 += dot4(wv, q[3][s]);
            }
            #pragma unroll
            for (int o = 16; o > 0; o >>= 1) {
                p0 += __shfl_xor_sync(0xffffffffu, p0, o);
                p1 += __shfl_xor_sync(0xffffffffu, p1, o);
                p2 += __shfl_xor_sync(0xffffffffu, p2, o);
                p3 += __shfl_xor_sync(0xffffffffu, p3, o);
            }
            if (lane == 0) {
                atomicAdd(&Y[0 * ys + r0 + rb + i], p0);
                atomicAdd(&Y[1 * ys + r0 + rb + i], p1);
                atomicAdd(&Y[2 * ys + r0 + rb + i], p2);
                atomicAdd(&Y[3 * ys + r0 + rb + i], p3);
            }
        }
        BAR_ARRIVE(bempt + buf * 8);
        if (++buf == TRNB) { buf = 0; ph ^= 1; }
    }
}

// ==================== flash: persistent ring + per-row online softmax ======
__global__ __launch_bounds__(THR) void k_flash(
    const float* __restrict__ x, const float* __restrict__ past)
{
    int b    = blockIdx.y;
    int cx   = blockIdx.x;
    int tid  = threadIdx.x;
    int wid  = tid >> 5;
    int lane = tid & 31;
    extern __shared__ __align__(16) unsigned char sm[];
    float4* bufs = (float4*)sm;
    float*  sred = (float*)(sm + NBUF * BUFB);        // [2][8]
    uint32_t sbase = s2u(sm);
    uint32_t bfull = sbase + NBUF * BUFB + 64;
    uint32_t bempt = bfull + 64;

    int r0 = (int)(((long long)cx * STOT) / NFB);
    int r1 = (int)(((long long)(cx + 1) * STOT) / NFB);
    int R  = r1 - r0;

    if (tid == 0) {
        #pragma unroll
        for (int i = 0; i < NBUF; i++) { BAR_INIT(bfull + i * 8, 1); BAR_INIT(bempt + i * 8, NC); }
    }
    __syncthreads();
    FENCE_ASYNC();

    if (tid >= NC) {
        int pl = tid - NC;
        if (pl < NBUF) {
            uint32_t php = 1;
            for (int rr = pl; rr < R; rr += NBUF) {
                int s = r0 + rr;
                const float* src = (s < SP) ? past + ((size_t)b * SP + s) * DM
                                            : x + (size_t)b * DM;
                bar_wait(bempt + pl * 8, php);
                BAR_EXPECT(bfull + pl * 8, BUFB);
                BULK_G2S(sbase + pl * BUFB, src, BUFB, bfull + pl * 8);
                php ^= 1;
            }
        }
        return;
    }

    const float4* t4 = (const float4*)(g_t + (size_t)b * DM);
    float4 tv[4];
    #pragma unroll
    for (int s = 0; s < 4; s++) tv[s] = t4[tid + 256 * s];

    float m = -INFINITY, l = 0.f;
    float4 A[4] = {{0,0,0,0},{0,0,0,0},{0,0,0,0},{0,0,0,0}};

    int buf = 0; uint32_t ph = 0;
    for (int rr = 0; rr < R; rr++) {
        bar_wait(bfull + buf * 8, ph);
        float4 v[4];
        #pragma unroll
        for (int s = 0; s < 4; s++) v[s] = bufs[buf * 1024 + tid + 256 * s];

        float p = dot4(v[0], tv[0]) + dot4(v[1], tv[1])
                + dot4(v[2], tv[2]) + dot4(v[3], tv[3]);
        #pragma unroll
        for (int o = 16; o > 0; o >>= 1) p += __shfl_xor_sync(0xffffffffu, p, o);
        if (lane == 0) sred[(rr & 1) * 8 + wid] = p;
        CBAR();
        const float* sr = sred + (rr & 1) * 8;
        float score = sr[0] + sr[1] + sr[2] + sr[3] + sr[4] + sr[5] + sr[6] + sr[7];

        float mn   = fmaxf(m, score);
        float corr = __expf(m - mn);
        float e    = __expf(score - mn);
        l = l * corr + e;
        #pragma unroll
        for (int s = 0; s < 4; s++) {
            A[s].x = A[s].x * corr + e * v[s].x;
            A[s].y = A[s].y * corr + e * v[s].y;
            A[s].z = A[s].z * corr + e * v[s].z;
            A[s].w = A[s].w * corr + e * v[s].w;
        }
        m = mn;
        BAR_ARRIVE(bempt + buf * 8);
        if (++buf == NBUF) { buf = 0; ph ^= 1; }
    }

    float4* acc4 = (float4*)(g_acc + ((size_t)b * NFB + cx) * DM);
    #pragma unroll
    for (int s = 0; s < 4; s++) acc4[tid + 256 * s] = A[s];
    if (tid == 0) { g_m[b * NFB + cx] = m; g_l[b * NFB + cx] = l; }
}

// ==================== combine 74 partials (+stats, Linv applied) ===========
__global__ __launch_bounds__(256) void k_combine() {
    int b   = blockIdx.y;
    int tid = threadIdx.x;
    __shared__ float smv[NFB], slv[NFB], swv[NFB];
    __shared__ float sM, sLinv;

    if (tid < NFB) { smv[tid] = g_m[b * NFB + tid]; slv[tid] = g_l[b * NFB + tid]; }
    __syncthreads();
    if (tid == 0) {
        float M = -INFINITY;
        for (int c = 0; c < NFB; c++) M = fmaxf(M, smv[c]);
        sM = M;
    }
    __syncthreads();
    if (tid < NFB) swv[tid] = __expf(smv[tid] - sM);
    __syncthreads();
    if (tid == 0) {
        float L = 0.f;
        for (int c = 0; c < NFB; c++) L += swv[c] * slv[c];
        sLinv = 1.f / L;
    }
    __syncthreads();

    int d = blockIdx.x * 256 + tid;
    const float* accp = g_acc + (size_t)b * NFB * DM + d;
    float s = 0.f;
    #pragma unroll 2
    for (int c = 0; c < NFB; c++) s += swv[c] * accp[(size_t)c * DM];
    g_p[b * DM + d] = s * sLinv;
}

// ==================== small forward gemv ====================
__global__ __launch_bounds__(256) void k_gemv4(
    const float* __restrict__ X, int xstride,
    const float* __restrict__ W, int ldw,
    float* __restrict__ Y, int ystride,
    int K, int N, int kchunk)
{
    const int N4 = N >> 2;
    const int ldw4 = ldw >> 2;
    int tid = threadIdx.x;
    int j4  = blockIdx.x * blockDim.x + tid;
    int d0  = blockIdx.y * kchunk;
    int d1  = min(K, d0 + kchunk);
    int nk  = d1 - d0;

    __shared__ float sx[BB][64];
    for (int i = tid; i < BB * nk; i += blockDim.x) {
        int bb = i / nk, kk = i - bb * nk;
        sx[bb][kk] = X[bb * xstride + d0 + kk];
    }
    __syncthreads();
    if (j4 >= N4) return;

    const float4* W4 = (const float4*)W;
    float4 a0 = {0,0,0,0}, a1 = a0, a2 = a0, a3 = a0;

    int k = 0;
    for (; k + 16 <= nk; k += 16) {
        float4 wv[16];
        #pragma unroll
        for (int i = 0; i < 16; i++)
            wv[i] = W4[(size_t)(d0 + k + i) * ldw4 + j4];
        #pragma unroll
        for (int i = 0; i < 16; i++) {
            fma4(a0, sx[0][k + i], wv[i]); fma4(a1, sx[1][k + i], wv[i]);
            fma4(a2, sx[2][k + i], wv[i]); fma4(a3, sx[3][k + i], wv[i]);
        }
    }
    for (; k < nk; k++) {
        float4 wv = W4[(size_t)(d0 + k) * ldw4 + j4];
        fma4(a0, sx[0][k], wv); fma4(a1, sx[1][k], wv);
        fma4(a2, sx[2][k], wv); fma4(a3, sx[3][k], wv);
    }

    int j = j4 * 4;
    atomicAdd(&Y[0 * ystride + j + 0], a0.x); atomicAdd(&Y[0 * ystride + j + 1], a0.y);
    atomicAdd(&Y[0 * ystride + j + 2], a0.z); atomicAdd(&Y[0 * ystride + j + 3], a0.w);
    atomicAdd(&Y[1 * ystride + j + 0], a1.x); atomicAdd(&Y[1 * ystride + j + 1], a1.y);
    atomicAdd(&Y[1 * ystride + j + 2], a1.z); atomicAdd(&Y[1 * ystride + j + 3], a1.w);
    atomicAdd(&Y[2 * ystride + j + 0], a2.x); atomicAdd(&Y[2 * ystride + j + 1], a2.y);
    atomicAdd(&Y[2 * ystride + j + 2], a2.z); atomicAdd(&Y[2 * ystride + j + 3], a2.w);
    atomicAdd(&Y[3 * ystride + j + 0], a3.x); atomicAdd(&Y[3 * ystride + j + 1], a3.y);
    atomicAdd(&Y[3 * ystride + j + 2], a3.z); atomicAdd(&Y[3 * ystride + j + 3], a3.w);
}

// ==================== small transposed gemv (step 7) ==============
__global__ __launch_bounds__(256) void k_gemv_t_s(
    const float* __restrict__ X, int xstride,
    const float* __restrict__ W, int ldw,
    float* __restrict__ Y, int ystride,
    int rows, int cols, float scalev)
{
    int gw   = (blockIdx.x * blockDim.x + threadIdx.x) >> 5;
    int lane = threadIdx.x & 31;
    if (gw >= rows) return;
    const float4* wp = (const float4*)(W + (size_t)gw * ldw);
    const float4* X4 = (const float4*)X;
    int cols4 = cols >> 2;
    int x4s   = xstride >> 2;

    float s0 = 0.f, s1 = 0.f, s2 = 0.f, s3 = 0.f;
    for (int c4 = lane; c4 < cols4; c4 += 32) {
        float4 wv = __ldg(&wp[c4]);
        s0 += dot4(wv, __ldg(&X4[0 * x4s + c4]));
        s1 += dot4(wv, __ldg(&X4[1 * x4s + c4]));
        s2 += dot4(wv, __ldg(&X4[2 * x4s + c4]));
        s3 += dot4(wv, __ldg(&X4[3 * x4s + c4]));
    }
    #pragma unroll
    for (int o = 16; o > 0; o >>= 1) {
        s0 += __shfl_xor_sync(0xffffffffu, s0, o);
        s1 += __shfl_xor_sync(0xffffffffu, s1, o);
        s2 += __shfl_xor_sync(0xffffffffu, s2, o);
        s3 += __shfl_xor_sync(0xffffffffu, s3, o);
    }
    if (lane == 0) {
        Y[0 * ystride + gw] = scalev * (Y[0 * ystride + gw] + s0);
        Y[1 * ystride + gw] = scalev * (Y[1 * ystride + gw] + s1);
        Y[2 * ystride + gw] = scalev * (Y[2 * ystride + gw] + s2);
        Y[3 * ystride + gw] = scalev * (Y[3 * ystride + gw] + s3);
    }
}

// ----------------------------------------------------------------------------
extern "C" void kernel_launch(void* const* d_in, const int* in_sizes, int n_in,
                              void* d_out, int out_size)
{
    const float* x    = (const float*)d_in[0];
    const float* past = (const float*)d_in[1];
    const float* Wdq  = (const float*)d_in[2];
    const float* Wuq  = (const float*)d_in[3];
    const float* Wqr  = (const float*)d_in[4];
    const float* Wdkv = (const float*)d_in[5];
    const float* Wkr  = (const float*)d_in[6];
    const float* F    = (const float*)d_in[7];
    const float* Wo   = (const float*)d_in[8];
    float* out = (float*)d_out;

    const float scale = 1.0f / sqrtf(2.0f * (float)DM);

    float *pCq, *pQc, *pQr, *pu, *pt, *pp, *pa, *pav;
    cudaGetSymbolAddress((void**)&pCq, g_Cq);
    cudaGetSymbolAddress((void**)&pQc, g_Qc);
    cudaGetSymbolAddress((void**)&pQr, g_Qr);
    cudaGetSymbolAddress((void**)&pu,  g_u);
    cudaGetSymbolAddress((void**)&pt,  g_t);
    cudaGetSymbolAddress((void**)&pp,  g_p);
    cudaGetSymbolAddress((void**)&pa,  g_a);
    cudaGetSymbolAddress((void**)&pav, g_av);

    const int FW_SMEM = FWNB * FWBUF + 2048 + 128;
    const int TR_SMEM = TRNB * FWBUF + 128;
    const int FL_SMEM = NBUF * BUFB + 64 + 128;
    cudaFuncSetAttribute(k_fw,    cudaFuncAttributeMaxDynamicSharedMemorySize, FW_SMEM);
    cudaFuncSetAttribute(k_tr,    cudaFuncAttributeMaxDynamicSharedMemorySize, TR_SMEM);
    cudaFuncSetAttribute(k_flash, cudaFuncAttributeMaxDynamicSharedMemorySize, FL_SMEM);

    // 1) zero atomic targets
    k_zero<<<128, 256>>>(out);

    // 2) Cq = x @ Wdq                   (64 MB, column-split)
    k_fw<<<dim3(FWK, FWC, 1), THR, FW_SMEM>>>(x, Wdq, Wdq, pCq, pCq);
    // 3+4) Qc = Cq @ Wuq ; Qr = Cq @ Wqr (128 MB)
    k_fw<<<dim3(FWK, FWC, 2), THR, FW_SMEM>>>(pCq, Wuq, Wqr, pQc, pQr);
    // 5+6) t += Wkr @ Qr ; u += F_ku @ Qc (72 MB, merged)
    k_tr<<<424, THR, TR_SMEM>>>(pQr, Wkr, (size_t)DM, pt, DM, DM, 296,
                                pQc, F, (size_t)(2 * DM), pu, LD, LD, 128);
    // 7) t = scale * (t + Wdkv @ u)     (8 MB)
    k_gemv_t_s<<<512, 256>>>(pu, LD, Wdkv, LD, pt, DM, DM, LD, scale);

    // 8) flash over [past_x; x]         (268 MB)
    k_flash<<<dim3(NFB, BB), THR, FL_SMEM>>>(x, past);
    // 9) combine 74 partials (+stats)
    k_combine<<<dim3(16, BB), 256>>>();

    // 10) a = p @ Wdkv                  (8 MB)
    k_gemv4<<<dim3(1, 64), 256>>>(pp, DM, Wdkv, LD, pa, LD, DM, LD, 64);
    // 11) attn_v = a @ F[:, DM:]        (8 MB)
    k_gemv4<<<dim3(4, 8), 256>>>(pa, LD, F + DM, 2 * DM, pav, DM, LD, DM, 64);
    // 12) out = attn_v @ Wo             (64 MB, column-split)
    k_fw<<<dim3(FWK, FWC, 1), THR, FW_SMEM>>>(pav, Wo, Wo, out, out);
}